// round 3
// baseline (speedup 1.0000x reference)
#include <cuda_runtime.h>
#include <math.h>

// ---------------- device scratch (no allocation allowed) ----------------
__device__ __align__(16) float g_v1[256];
__device__ __align__(16) float g_v2[256];
__device__ float g_p1[128];
__device__ float g_p2[128];

// ---------------- prep: v1 = W@a1, v2 = W@a2, pos1/pos2 -----------------
// 1024 threads, 1 CTA. Fast path: double range-reduction + MUFU __sincosf.
__global__ void __launch_bounds__(1024) prep_kernel(const float* __restrict__ W,
                                                    const float* __restrict__ a) {
    __shared__ float v1s[256], v2s[256];
    __shared__ float a1s[256], a2s[256];
    __shared__ float psum1[1024], psum2[1024];
    const int t = threadIdx.x;

    if (t < 256) { a1s[t] = a[t]; a2s[t] = a[256 + t]; }
    __syncthreads();

    if (t < 256) {
        float acc1 = 0.f, acc2 = 0.f;
        const float4* Wv = (const float4*)(W + t * 256);
        const float4* A1 = (const float4*)a1s;
        const float4* A2 = (const float4*)a2s;
#pragma unroll 8
        for (int q = 0; q < 64; q++) {
            float4 w = Wv[q];
            float4 b1 = A1[q], b2 = A2[q];
            acc1 += w.x * b1.x + w.y * b1.y + w.z * b1.z + w.w * b1.w;
            acc2 += w.x * b2.x + w.y * b2.y + w.z * b2.z + w.w * b2.w;
        }
        v1s[t] = acc1; v2s[t] = acc2;
        g_v1[t] = acc1; g_v2[t] = acc2;
    }
    __syncthreads();

    // pos partials: thread handles n = t&127, pair index p in [seg*16, seg*16+16)
    {
        const int n = t & 127;
        const int seg = t >> 7;
        const double TWO_PI = 6.283185307179586476925286766559;
        const double INV_TWO_PI = 0.15915494309189533576888376337251;
        float p1 = 0.f, p2 = 0.f;
#pragma unroll
        for (int pp = 0; pp < 16; pp++) {
            const int p = seg * 16 + pp;                  // f = 2p (sin), 2p+1 (cos)
            // mirror reference f32 math: angle = n / 10000^{2p/256}
            float rp = powf(10000.0f, (float)(2 * p) * (1.0f / 256.0f));
            float angle = (float)n / rp;
            // exact-enough reduction: angle mod 2pi in double, then MUFU sincos
            double ad = (double)angle;
            double k = rint(ad * INV_TWO_PI);
            float red = (float)(ad - k * TWO_PI);
            float s, c;
            __sincosf(red, &s, &c);
            p1 += s * v1s[2 * p] + c * v1s[2 * p + 1];
            p2 += s * v2s[2 * p] + c * v2s[2 * p + 1];
        }
        psum1[t] = p1; psum2[t] = p2;
    }
    __syncthreads();

    if (t < 128) {
        float p1 = 0.f, p2 = 0.f;
#pragma unroll
        for (int s = 0; s < 8; s++) { p1 += psum1[s * 128 + t]; p2 += psum2[s * 128 + t]; }
        g_p1[t] = 1000.0f * p1;
        g_p2[t] = 1000.0f * p2;
    }
}

// ---------------- fused main kernel: 1 CTA per batch --------------------
// Scale-invariant softmax: out[i,j] = mask * E[i,j] / S_j, where
//   rows i<64 : E = elt[2i + (j>=64)]
//   rows i>=64: E = elu[j]
__global__ void __launch_bounds__(256, 8) gat_kernel(
    const float* __restrict__ src,
    const float* __restrict__ adj,
    float* __restrict__ out)
{
    __shared__ float s1s[128], s2s[128];
    __shared__ float elt[128], elu[128];
    __shared__ float red[256];
    __shared__ __align__(16) float sv1[256], sv2[256];

    const int b   = blockIdx.x;
    const int tid = threadIdx.x;
    const int w   = tid >> 5;
    const int l   = tid & 31;

    // stage v1/v2 into smem (keeps hot-loop register count under the 32-reg cap)
    if (tid < 128) {
        ((float2*)sv1)[tid] = ((const float2*)g_v1)[tid];
        ((float2*)sv2)[tid] = ((const float2*)g_v2)[tid];
    }
    __syncthreads();

    // -- phase A: s1[n] = src[b,n,:].v1 + pos1[n]  (8 warps x 16 rows) --
    const float4* sbase = (const float4*)(src + (size_t)b * 32768);
    const float4* v1v = (const float4*)sv1;
    const float4* v2v = (const float4*)sv2;
#pragma unroll 1
    for (int r = 0; r < 16; r++) {
        int n = w * 16 + r;
        float4 x0 = sbase[n * 64 + l];
        float4 x1 = sbase[n * 64 + 32 + l];
        float4 va = v1v[l];
        float4 vb = v1v[l + 32];
        float acc1 = x0.x * va.x + x0.y * va.y + x0.z * va.z + x0.w * va.w
                   + x1.x * vb.x + x1.y * vb.y + x1.z * vb.z + x1.w * vb.w;
        va = v2v[l];
        vb = v2v[l + 32];
        float acc2 = x0.x * va.x + x0.y * va.y + x0.z * va.z + x0.w * va.w
                   + x1.x * vb.x + x1.y * vb.y + x1.z * vb.z + x1.w * vb.w;
#pragma unroll
        for (int off = 16; off; off >>= 1) {
            acc1 += __shfl_xor_sync(0xFFFFFFFFu, acc1, off);
            acc2 += __shfl_xor_sync(0xFFFFFFFFu, acc2, off);
        }
        if (l == 0) {
            s1s[n] = acc1 + g_p1[n];
            s2s[n] = acc2 + g_p2[n];
        }
    }
    __syncthreads();

    // -- phase B: exp(leaky(t)), exp(leaky(u)) --
    if (tid < 128) {
        int m = tid;
        float t = s1s[m] + s2s[m];
        t = (t > 0.f) ? t : 0.2f * t;
        elt[m] = expf(t);
        float u = s1s[(2 * m) & 127] + s2s[(2 * m + 1) & 127];
        u = (u > 0.f) ? u : 0.2f * u;
        elu[m] = expf(u);
    }
    __syncthreads();

    // -- phase C: read adj column slice, build mask, accumulate S --
    const int j = tid & 127;
    const int h = tid >> 7;                       // h=0: rows 0..63, h=1: rows 64..127
    const float* adjb = adj + (size_t)b * 16384 + (size_t)(h << 13) + j;

    unsigned m0 = 0, m1 = 0;
    float S = 0.f;
    if (h == 0) {
        const int jhi = j >> 6;
#pragma unroll
        for (int ii = 0; ii < 32; ii++) {
            float av = __ldg(adjb + ii * 128);
            if (av > 0.f) { m0 |= 1u << ii; S += elt[2 * ii + jhi]; }
        }
#pragma unroll
        for (int ii = 0; ii < 32; ii++) {
            float av = __ldg(adjb + (32 + ii) * 128);
            if (av > 0.f) { m1 |= 1u << ii; S += elt[64 + 2 * ii + jhi]; }
        }
    } else {
#pragma unroll
        for (int ii = 0; ii < 32; ii++) {
            float av = __ldg(adjb + ii * 128);
            m0 |= (av > 0.f ? 1u : 0u) << ii;
        }
#pragma unroll
        for (int ii = 0; ii < 32; ii++) {
            float av = __ldg(adjb + (32 + ii) * 128);
            m1 |= (av > 0.f ? 1u : 0u) << ii;
        }
        S = (float)(__popc(m0) + __popc(m1)) * elu[j];
    }
    red[tid] = S;
    __syncthreads();
    const float Stot = red[j] + red[j + 128];
    // all-masked column: reference softmax of equal NEG values -> uniform 1/128
    const float inv = (Stot > 0.f) ? (1.0f / Stot) : 0.f;
    const float add = (Stot > 0.f) ? 0.f : 0.0078125f;

    // -- phase D: write-out (coalesced in j) --
    float* outp = out + (size_t)b * 16384 + (size_t)(h << 13) + j;
    if (h == 0) {
        const int jhi = j >> 6;
#pragma unroll
        for (int ii = 0; ii < 32; ii++) {
            float v = ((m0 >> ii) & 1u) ? elt[2 * ii + jhi] * inv : 0.f;
            outp[ii * 128] = v + add;
        }
#pragma unroll
        for (int ii = 0; ii < 32; ii++) {
            float v = ((m1 >> ii) & 1u) ? elt[64 + 2 * ii + jhi] * inv : 0.f;
            outp[(32 + ii) * 128] = v + add;
        }
    } else {
        const float c = elu[j] * inv;
#pragma unroll
        for (int ii = 0; ii < 32; ii++) {
            float v = ((m0 >> ii) & 1u) ? c : 0.f;
            outp[ii * 128] = v + add;
        }
#pragma unroll
        for (int ii = 0; ii < 32; ii++) {
            float v = ((m1 >> ii) & 1u) ? c : 0.f;
            outp[(32 + ii) * 128] = v + add;
        }
    }
}

// ---------------- launcher ----------------
extern "C" void kernel_launch(void* const* d_in, const int* in_sizes, int n_in,
                              void* d_out, int out_size) {
    const float* src = (const float*)d_in[0];   // (2048,128,256)
    const float* W   = (const float*)d_in[1];   // (256,256)
    const float* a   = (const float*)d_in[2];   // (512,1)
    const float* adj = (const float*)d_in[3];   // (2048,128,128)
    float* out = (float*)d_out;                 // (2048,128,128)

    prep_kernel<<<1, 1024>>>(W, a);
    gat_kernel<<<2048, 256>>>(src, adj, out);
}

// round 4
// speedup vs baseline: 1.2145x; 1.2145x over previous
#include <cuda_runtime.h>
#include <math.h>

// ---------------- device scratch (no allocation allowed) ----------------
__device__ __align__(16) float g_v1[256];
__device__ __align__(16) float g_v2[256];
__device__ float g_p1[128];
__device__ float g_p2[128];

// ---------------- prep: v1 = W@a1, v2 = W@a2, pos1/pos2 -----------------
// 1024 threads, 1 CTA. invd via 128 parallel double pow (hoisted), then
// double range-reduction + MUFU __sincosf in the hot loop.
__global__ void __launch_bounds__(1024) prep_kernel(const float* __restrict__ W,
                                                    const float* __restrict__ a) {
    __shared__ float v1s[256], v2s[256];
    __shared__ float a1s[256], a2s[256];
    __shared__ double invd[128];
    __shared__ float psum1[1024], psum2[1024];
    const int t = threadIdx.x;

    if (t < 256) { a1s[t] = a[t]; a2s[t] = a[256 + t]; }
    if (t < 128) invd[t] = pow(10000.0, -(double)(2 * t) / 256.0);
    __syncthreads();

    if (t < 256) {
        float acc1 = 0.f, acc2 = 0.f;
        const float4* Wv = (const float4*)(W + t * 256);
        const float4* A1 = (const float4*)a1s;
        const float4* A2 = (const float4*)a2s;
#pragma unroll 8
        for (int q = 0; q < 64; q++) {
            float4 w = Wv[q];
            float4 b1 = A1[q], b2 = A2[q];
            acc1 += w.x * b1.x + w.y * b1.y + w.z * b1.z + w.w * b1.w;
            acc2 += w.x * b2.x + w.y * b2.y + w.z * b2.z + w.w * b2.w;
        }
        v1s[t] = acc1; v2s[t] = acc2;
        g_v1[t] = acc1; g_v2[t] = acc2;
    }
    __syncthreads();

    // pos partials: thread handles n = t&127, pair index p in [seg*16, seg*16+16)
    {
        const int n = t & 127;
        const int seg = t >> 7;
        const double TWO_PI = 6.283185307179586476925286766559;
        const double INV_TWO_PI = 0.15915494309189533576888376337251;
        float p1 = 0.f, p2 = 0.f;
#pragma unroll
        for (int pp = 0; pp < 16; pp++) {
            const int p = seg * 16 + pp;                  // f = 2p (sin), 2p+1 (cos)
            double ad = (double)n * invd[p];              // angle (double)
            double k = rint(ad * INV_TWO_PI);
            float red = (float)(ad - k * TWO_PI);         // angle mod 2pi
            float s, c;
            __sincosf(red, &s, &c);                        // MUFU
            p1 += s * v1s[2 * p] + c * v1s[2 * p + 1];
            p2 += s * v2s[2 * p] + c * v2s[2 * p + 1];
        }
        psum1[t] = p1; psum2[t] = p2;
    }
    __syncthreads();

    if (t < 128) {
        float p1 = 0.f, p2 = 0.f;
#pragma unroll
        for (int s = 0; s < 8; s++) { p1 += psum1[s * 128 + t]; p2 += psum2[s * 128 + t]; }
        g_p1[t] = 1000.0f * p1;
        g_p2[t] = 1000.0f * p2;
    }
}

// ---------------- fused main kernel: 1 CTA per batch --------------------
// Scale-invariant softmax: out[i,j] = mask * E[i,j] / S_j, where
//   rows i<64 : E = elt[2i + (j>=64)]
//   rows i>=64: E = elu[j]
__global__ void __launch_bounds__(256) gat_kernel(
    const float* __restrict__ src,
    const float* __restrict__ adj,
    float* __restrict__ out)
{
    __shared__ float s1s[128], s2s[128];
    __shared__ float elt[128], elu[128];
    __shared__ float red[256];

    const int b   = blockIdx.x;
    const int tid = threadIdx.x;
    const int w   = tid >> 5;
    const int l   = tid & 31;

    // -- phase 0: adj masks (independent of everything; LDGs overlap phase A) --
    const int j = tid & 127;
    const int h = tid >> 7;                       // h=0: rows 0..63, h=1: rows 64..127
    const float* adjb = adj + (size_t)b * 16384 + (size_t)(h << 13) + j;

    unsigned m0 = 0, m1 = 0;
#pragma unroll
    for (int ii = 0; ii < 32; ii++) {
        float av = __ldg(adjb + ii * 128);
        m0 |= (av > 0.f ? 1u : 0u) << ii;
    }
#pragma unroll
    for (int ii = 0; ii < 32; ii++) {
        float av = __ldg(adjb + (32 + ii) * 128);
        m1 |= (av > 0.f ? 1u : 0u) << ii;
    }

    // -- phase A: s1[n] = src[b,n,:].v1 + pos1[n]  (8 warps x 16 rows) --
    const float4* v1p = (const float4*)g_v1;
    const float4* v2p = (const float4*)g_v2;
    float4 v1a = v1p[l], v1b = v1p[l + 32];
    float4 v2a = v2p[l], v2b = v2p[l + 32];

    const float4* sbase = (const float4*)(src + (size_t)b * 32768);
#pragma unroll 2
    for (int r = 0; r < 16; r++) {
        int n = w * 16 + r;
        float4 x0 = sbase[n * 64 + l];
        float4 x1 = sbase[n * 64 + 32 + l];
        float acc1 = x0.x * v1a.x + x0.y * v1a.y + x0.z * v1a.z + x0.w * v1a.w
                   + x1.x * v1b.x + x1.y * v1b.y + x1.z * v1b.z + x1.w * v1b.w;
        float acc2 = x0.x * v2a.x + x0.y * v2a.y + x0.z * v2a.z + x0.w * v2a.w
                   + x1.x * v2b.x + x1.y * v2b.y + x1.z * v2b.z + x1.w * v2b.w;
#pragma unroll
        for (int off = 16; off; off >>= 1) {
            acc1 += __shfl_xor_sync(0xFFFFFFFFu, acc1, off);
            acc2 += __shfl_xor_sync(0xFFFFFFFFu, acc2, off);
        }
        if (l == 0) {
            s1s[n] = acc1 + g_p1[n];
            s2s[n] = acc2 + g_p2[n];
        }
    }
    __syncthreads();

    // -- phase B: exp(leaky(t)), exp(leaky(u)) --
    if (tid < 128) {
        int m = tid;
        float t = s1s[m] + s2s[m];
        t = (t > 0.f) ? t : 0.2f * t;
        elt[m] = expf(t);
        float u = s1s[(2 * m) & 127] + s2s[(2 * m + 1) & 127];
        u = (u > 0.f) ? u : 0.2f * u;
        elu[m] = expf(u);
    }
    __syncthreads();

    // -- phase C: column sum S from masks (LDS only) --
    float S = 0.f;
    if (h == 0) {
        const int jhi = j >> 6;
#pragma unroll
        for (int ii = 0; ii < 32; ii++)
            if ((m0 >> ii) & 1u) S += elt[2 * ii + jhi];
#pragma unroll
        for (int ii = 0; ii < 32; ii++)
            if ((m1 >> ii) & 1u) S += elt[64 + 2 * ii + jhi];
    } else {
        S = (float)(__popc(m0) + __popc(m1)) * elu[j];
    }
    red[tid] = S;
    __syncthreads();
    const float Stot = red[j] + red[j + 128];
    // all-masked column: reference softmax of equal NEG values -> uniform 1/128
    const float inv = (Stot > 0.f) ? (1.0f / Stot) : 0.f;
    const float add = (Stot > 0.f) ? 0.f : 0.0078125f;

    // -- phase D: write-out (coalesced in j) --
    float* outp = out + (size_t)b * 16384 + (size_t)(h << 13) + j;
    if (h == 0) {
        const int jhi = j >> 6;
#pragma unroll
        for (int ii = 0; ii < 32; ii++) {
            float v = ((m0 >> ii) & 1u) ? elt[2 * ii + jhi] * inv : 0.f;
            outp[ii * 128] = v + add;
        }
#pragma unroll
        for (int ii = 0; ii < 32; ii++) {
            float v = ((m1 >> ii) & 1u) ? elt[64 + 2 * ii + jhi] * inv : 0.f;
            outp[(32 + ii) * 128] = v + add;
        }
    } else {
        const float c = elu[j] * inv;
#pragma unroll
        for (int ii = 0; ii < 32; ii++) {
            float v = ((m0 >> ii) & 1u) ? c : 0.f;
            outp[ii * 128] = v + add;
        }
#pragma unroll
        for (int ii = 0; ii < 32; ii++) {
            float v = ((m1 >> ii) & 1u) ? c : 0.f;
            outp[(32 + ii) * 128] = v + add;
        }
    }
}

// ---------------- launcher ----------------
extern "C" void kernel_launch(void* const* d_in, const int* in_sizes, int n_in,
                              void* d_out, int out_size) {
    const float* src = (const float*)d_in[0];   // (2048,128,256)
    const float* W   = (const float*)d_in[1];   // (256,256)
    const float* a   = (const float*)d_in[2];   // (512,1)
    const float* adj = (const float*)d_in[3];   // (2048,128,128)
    float* out = (float*)d_out;                 // (2048,128,128)

    prep_kernel<<<1, 1024>>>(W, a);
    gat_kernel<<<2048, 256>>>(src, adj, out);
}

// round 5
// speedup vs baseline: 1.5532x; 1.2789x over previous
#include <cuda_runtime.h>
#include <math.h>

// ---------------- device scratch (no allocation allowed) ----------------
__device__ __align__(16) float g_v1[256];
__device__ __align__(16) float g_v2[256];
__device__ float g_p1[128];
__device__ float g_p2[128];

// ---------------- prep_v: v1 = W@a1, v2 = W@a2 (1 CTA, 256 thr) ---------
__global__ void __launch_bounds__(256) prep_v_kernel(const float* __restrict__ W,
                                                     const float* __restrict__ a) {
    __shared__ float a1s[256], a2s[256];
    const int t = threadIdx.x;
    a1s[t] = a[t];
    a2s[t] = a[256 + t];
    __syncthreads();

    float acc1 = 0.f, acc2 = 0.f;
    const float4* Wv = (const float4*)(W + t * 256);
    const float4* A1 = (const float4*)a1s;
    const float4* A2 = (const float4*)a2s;
#pragma unroll 8
    for (int q = 0; q < 64; q++) {
        float4 w = Wv[q];
        float4 b1 = A1[q], b2 = A2[q];
        acc1 += w.x * b1.x + w.y * b1.y + w.z * b1.z + w.w * b1.w;
        acc2 += w.x * b2.x + w.y * b2.y + w.z * b2.z + w.w * b2.w;
    }
    g_v1[t] = acc1;
    g_v2[t] = acc2;
}

// ---------------- prep_pos: 128 CTAs (one per n), 128 thr (one per pair p)
// p1[n] = 1000 * sum_p [ sin(n*invd_p)*v1[2p] + cos(n*invd_p)*v1[2p+1] ]
__global__ void __launch_bounds__(128) prep_pos_kernel() {
    __shared__ float r1[4], r2[4];
    const int n = blockIdx.x;
    const int p = threadIdx.x;       // frequency pair index
    const int l = p & 31;
    const int w = p >> 5;

    const double TWO_PI     = 6.283185307179586476925286766559;
    const double INV_TWO_PI = 0.15915494309189533576888376337251;

    // one accurate pow + one MUFU sincos per thread
    double invd = pow(10000.0, -(double)(2 * p) / 256.0);
    double ad = (double)n * invd;
    double k = rint(ad * INV_TWO_PI);
    float red = (float)(ad - k * TWO_PI);
    float s, c;
    __sincosf(red, &s, &c);

    float t1 = s * g_v1[2 * p] + c * g_v1[2 * p + 1];
    float t2 = s * g_v2[2 * p] + c * g_v2[2 * p + 1];

#pragma unroll
    for (int off = 16; off; off >>= 1) {
        t1 += __shfl_xor_sync(0xFFFFFFFFu, t1, off);
        t2 += __shfl_xor_sync(0xFFFFFFFFu, t2, off);
    }
    if (l == 0) { r1[w] = t1; r2[w] = t2; }
    __syncthreads();
    if (p == 0) {
        g_p1[n] = 1000.0f * (r1[0] + r1[1] + r1[2] + r1[3]);
        g_p2[n] = 1000.0f * (r2[0] + r2[1] + r2[2] + r2[3]);
    }
}

// ---------------- fused main kernel: 1 CTA per batch (R2 shape, verbatim)
// Scale-invariant softmax: out[i,j] = mask * E[i,j] / S_j, where
//   rows i<64 : E = elt[2i + (j>=64)]
//   rows i>=64: E = elu[j]
__global__ void __launch_bounds__(256) gat_kernel(
    const float* __restrict__ src,
    const float* __restrict__ adj,
    float* __restrict__ out)
{
    __shared__ float s1s[128], s2s[128];
    __shared__ float elt[128], elu[128];
    __shared__ float red[256];

    const int b   = blockIdx.x;
    const int tid = threadIdx.x;
    const int w   = tid >> 5;
    const int l   = tid & 31;

    // -- phase A: s1[n] = src[b,n,:].v1 + pos1[n]  (8 warps x 16 rows) --
    const float4* v1p = (const float4*)g_v1;
    const float4* v2p = (const float4*)g_v2;
    float4 v1a = v1p[l], v1b = v1p[l + 32];
    float4 v2a = v2p[l], v2b = v2p[l + 32];

    const float4* sbase = (const float4*)(src + (size_t)b * 32768);
#pragma unroll 2
    for (int r = 0; r < 16; r++) {
        int n = w * 16 + r;
        float4 x0 = sbase[n * 64 + l];
        float4 x1 = sbase[n * 64 + 32 + l];
        float acc1 = x0.x * v1a.x + x0.y * v1a.y + x0.z * v1a.z + x0.w * v1a.w
                   + x1.x * v1b.x + x1.y * v1b.y + x1.z * v1b.z + x1.w * v1b.w;
        float acc2 = x0.x * v2a.x + x0.y * v2a.y + x0.z * v2a.z + x0.w * v2a.w
                   + x1.x * v2b.x + x1.y * v2b.y + x1.z * v2b.z + x1.w * v2b.w;
#pragma unroll
        for (int off = 16; off; off >>= 1) {
            acc1 += __shfl_xor_sync(0xFFFFFFFFu, acc1, off);
            acc2 += __shfl_xor_sync(0xFFFFFFFFu, acc2, off);
        }
        if (l == 0) {
            s1s[n] = acc1 + g_p1[n];
            s2s[n] = acc2 + g_p2[n];
        }
    }
    __syncthreads();

    // -- phase B: exp(leaky(t)), exp(leaky(u)) --
    if (tid < 128) {
        int m = tid;
        float t = s1s[m] + s2s[m];
        t = (t > 0.f) ? t : 0.2f * t;
        elt[m] = expf(t);
        float u = s1s[(2 * m) & 127] + s2s[(2 * m + 1) & 127];
        u = (u > 0.f) ? u : 0.2f * u;
        elu[m] = expf(u);
    }
    __syncthreads();

    // -- phase C: read adj column slice, build mask, accumulate S --
    const int j = tid & 127;
    const int h = tid >> 7;                       // h=0: rows 0..63, h=1: rows 64..127
    const float* adjb = adj + (size_t)b * 16384 + (size_t)(h << 13) + j;

    unsigned m0 = 0, m1 = 0;
    float S = 0.f;
    if (h == 0) {
        const int jhi = j >> 6;
#pragma unroll
        for (int ii = 0; ii < 32; ii++) {
            float av = __ldg(adjb + ii * 128);
            if (av > 0.f) { m0 |= 1u << ii; S += elt[2 * ii + jhi]; }
        }
#pragma unroll
        for (int ii = 0; ii < 32; ii++) {
            float av = __ldg(adjb + (32 + ii) * 128);
            if (av > 0.f) { m1 |= 1u << ii; S += elt[64 + 2 * ii + jhi]; }
        }
    } else {
#pragma unroll
        for (int ii = 0; ii < 32; ii++) {
            float av = __ldg(adjb + ii * 128);
            m0 |= (av > 0.f ? 1u : 0u) << ii;
        }
#pragma unroll
        for (int ii = 0; ii < 32; ii++) {
            float av = __ldg(adjb + (32 + ii) * 128);
            m1 |= (av > 0.f ? 1u : 0u) << ii;
        }
        S = (float)(__popc(m0) + __popc(m1)) * elu[j];
    }
    red[tid] = S;
    __syncthreads();
    const float Stot = red[j] + red[j + 128];
    // all-masked column: reference softmax of equal NEG values -> uniform 1/128
    const float inv = (Stot > 0.f) ? (1.0f / Stot) : 0.f;
    const float add = (Stot > 0.f) ? 0.f : 0.0078125f;

    // -- phase D: write-out (coalesced in j) --
    float* outp = out + (size_t)b * 16384 + (size_t)(h << 13) + j;
    if (h == 0) {
        const int jhi = j >> 6;
#pragma unroll
        for (int ii = 0; ii < 32; ii++) {
            float v = ((m0 >> ii) & 1u) ? elt[2 * ii + jhi] * inv : 0.f;
            outp[ii * 128] = v + add;
        }
#pragma unroll
        for (int ii = 0; ii < 32; ii++) {
            float v = ((m1 >> ii) & 1u) ? elt[64 + 2 * ii + jhi] * inv : 0.f;
            outp[(32 + ii) * 128] = v + add;
        }
    } else {
        const float c = elu[j] * inv;
#pragma unroll
        for (int ii = 0; ii < 32; ii++) {
            float v = ((m0 >> ii) & 1u) ? c : 0.f;
            outp[ii * 128] = v + add;
        }
#pragma unroll
        for (int ii = 0; ii < 32; ii++) {
            float v = ((m1 >> ii) & 1u) ? c : 0.f;
            outp[(32 + ii) * 128] = v + add;
        }
    }
}

// ---------------- launcher ----------------
extern "C" void kernel_launch(void* const* d_in, const int* in_sizes, int n_in,
                              void* d_out, int out_size) {
    const float* src = (const float*)d_in[0];   // (2048,128,256)
    const float* W   = (const float*)d_in[1];   // (256,256)
    const float* a   = (const float*)d_in[2];   // (512,1)
    const float* adj = (const float*)d_in[3];   // (2048,128,128)
    float* out = (float*)d_out;                 // (2048,128,128)

    prep_v_kernel<<<1, 256>>>(W, a);
    prep_pos_kernel<<<128, 128>>>();
    gat_kernel<<<2048, 256>>>(src, adj, out);
}

// round 6
// speedup vs baseline: 1.7125x; 1.1026x over previous
#include <cuda_runtime.h>
#include <math.h>

// ---------------- device scratch (no allocation allowed) ----------------
__device__ __align__(16) float g_v1[256];
__device__ __align__(16) float g_v2[256];
__device__ float g_p1[128];
__device__ float g_p2[128];

// ---------------- prep_v: v = W@a, one warp per row (32 CTAs x 256 thr) --
__global__ void __launch_bounds__(256) prep_v_kernel(const float* __restrict__ W,
                                                     const float* __restrict__ a) {
    const int l   = threadIdx.x & 31;
    const int row = blockIdx.x * 8 + (threadIdx.x >> 5);

    const float4* Wr = (const float4*)(W + row * 256);
    float4 w0 = __ldg(Wr + 2 * l);
    float4 w1 = __ldg(Wr + 2 * l + 1);
    const float4* A1 = (const float4*)a;         // a[0..255]
    const float4* A2 = (const float4*)(a + 256); // a[256..511]
    float4 p0 = __ldg(A1 + 2 * l), p1 = __ldg(A1 + 2 * l + 1);
    float4 q0 = __ldg(A2 + 2 * l), q1 = __ldg(A2 + 2 * l + 1);

    float acc1 = w0.x * p0.x + w0.y * p0.y + w0.z * p0.z + w0.w * p0.w
               + w1.x * p1.x + w1.y * p1.y + w1.z * p1.z + w1.w * p1.w;
    float acc2 = w0.x * q0.x + w0.y * q0.y + w0.z * q0.z + w0.w * q0.w
               + w1.x * q1.x + w1.y * q1.y + w1.z * q1.z + w1.w * q1.w;
#pragma unroll
    for (int off = 16; off; off >>= 1) {
        acc1 += __shfl_xor_sync(0xFFFFFFFFu, acc1, off);
        acc2 += __shfl_xor_sync(0xFFFFFFFFu, acc2, off);
    }
    if (l == 0) { g_v1[row] = acc1; g_v2[row] = acc2; }
}

// ---------------- prep_pos: 128 CTAs (one per n), 128 thr (one per pair p)
__global__ void __launch_bounds__(128) prep_pos_kernel() {
    __shared__ float r1[4], r2[4];
    const int n = blockIdx.x;
    const int p = threadIdx.x;
    const int l = p & 31;
    const int w = p >> 5;

    const double TWO_PI     = 6.283185307179586476925286766559;
    const double INV_TWO_PI = 0.15915494309189533576888376337251;

    double invd = pow(10000.0, -(double)(2 * p) / 256.0);
    double ad = (double)n * invd;
    double k = rint(ad * INV_TWO_PI);
    float red = (float)(ad - k * TWO_PI);
    float s, c;
    __sincosf(red, &s, &c);

    float t1 = s * g_v1[2 * p] + c * g_v1[2 * p + 1];
    float t2 = s * g_v2[2 * p] + c * g_v2[2 * p + 1];
#pragma unroll
    for (int off = 16; off; off >>= 1) {
        t1 += __shfl_xor_sync(0xFFFFFFFFu, t1, off);
        t2 += __shfl_xor_sync(0xFFFFFFFFu, t2, off);
    }
    if (l == 0) { r1[w] = t1; r2[w] = t2; }
    __syncthreads();
    if (p == 0) {
        g_p1[n] = 1000.0f * (r1[0] + r1[1] + r1[2] + r1[3]);
        g_p2[n] = 1000.0f * (r2[0] + r2[1] + r2[2] + r2[3]);
    }
}

// ---------------- fused main kernel: 1 CTA per batch --------------------
// out[i,j] = mask * E[i,j] / S_j ; rows i<64: E=elt[2i+(j>=64)], i>=64: E=elu[j]
__global__ void __launch_bounds__(256) gat_kernel(
    const float* __restrict__ src,
    const float* __restrict__ adj,
    float* __restrict__ out)
{
    __shared__ float s1s[128], s2s[128];
    __shared__ float elt[128], elu[128];
    __shared__ __align__(16) float redS[8][128];
    __shared__ float invS[128];
    __shared__ float addS[128];

    const int b   = blockIdx.x;
    const int tid = threadIdx.x;
    const int w   = tid >> 5;
    const int l   = tid & 31;

    // -- phase A: s1[n] = src[b,n,:].v1 + pos1[n]  (8 warps x 16 rows) --
    const float4* v1p = (const float4*)g_v1;
    const float4* v2p = (const float4*)g_v2;
    float4 v1a = v1p[l], v1b = v1p[l + 32];
    float4 v2a = v2p[l], v2b = v2p[l + 32];

    const float4* sbase = (const float4*)(src + (size_t)b * 32768);
#pragma unroll 2
    for (int r = 0; r < 16; r++) {
        int n = w * 16 + r;
        float4 x0 = sbase[n * 64 + l];
        float4 x1 = sbase[n * 64 + 32 + l];
        float acc1 = x0.x * v1a.x + x0.y * v1a.y + x0.z * v1a.z + x0.w * v1a.w
                   + x1.x * v1b.x + x1.y * v1b.y + x1.z * v1b.z + x1.w * v1b.w;
        float acc2 = x0.x * v2a.x + x0.y * v2a.y + x0.z * v2a.z + x0.w * v2a.w
                   + x1.x * v2b.x + x1.y * v2b.y + x1.z * v2b.z + x1.w * v2b.w;
#pragma unroll
        for (int off = 16; off; off >>= 1) {
            acc1 += __shfl_xor_sync(0xFFFFFFFFu, acc1, off);
            acc2 += __shfl_xor_sync(0xFFFFFFFFu, acc2, off);
        }
        if (l == 0) {
            s1s[n] = acc1 + g_p1[n];
            s2s[n] = acc2 + g_p2[n];
        }
    }
    __syncthreads();

    // -- phase B: exp(leaky(t)), exp(leaky(u)) --
    if (tid < 128) {
        int m = tid;
        float t = s1s[m] + s2s[m];
        t = (t > 0.f) ? t : 0.2f * t;
        elt[m] = expf(t);
        float u = s1s[(2 * m) & 127] + s2s[(2 * m + 1) & 127];
        u = (u > 0.f) ? u : 0.2f * u;
        elu[m] = expf(u);
    }
    __syncthreads();

    // -- phase C: float4 adj loads; thread = (jgroup g, row-slice r8) --
    const int g  = tid & 31;          // columns 4g..4g+3
    const int r8 = tid >> 5;          // rows r8*16..r8*16+15
    const int j0 = g << 2;
    const float4* adjb = (const float4*)(adj + (size_t)b * 16384) + r8 * 16 * 32 + g;

    unsigned m01 = 0, m23 = 0;        // 16-bit masks for cols j0..j0+3
    float S0 = 0.f, S1 = 0.f, S2 = 0.f, S3 = 0.f;
    if (r8 < 4) {
        const int jhi = g >> 4;       // uniform: all 4 cols in same half
        const int ibase = r8 * 16;
#pragma unroll
        for (int rr = 0; rr < 16; rr++) {
            float4 av = __ldg(adjb + rr * 32);
            float ev = elt[2 * (ibase + rr) + jhi];
            if (av.x > 0.f) { m01 |= 1u << rr;        S0 += ev; }
            if (av.y > 0.f) { m01 |= 1u << (16 + rr); S1 += ev; }
            if (av.z > 0.f) { m23 |= 1u << rr;        S2 += ev; }
            if (av.w > 0.f) { m23 |= 1u << (16 + rr); S3 += ev; }
        }
    } else {
        int c0 = 0, c1 = 0, c2 = 0, c3 = 0;
#pragma unroll
        for (int rr = 0; rr < 16; rr++) {
            float4 av = __ldg(adjb + rr * 32);
            if (av.x > 0.f) { m01 |= 1u << rr;        c0++; }
            if (av.y > 0.f) { m01 |= 1u << (16 + rr); c1++; }
            if (av.z > 0.f) { m23 |= 1u << rr;        c2++; }
            if (av.w > 0.f) { m23 |= 1u << (16 + rr); c3++; }
        }
        S0 = (float)c0 * elu[j0];
        S1 = (float)c1 * elu[j0 + 1];
        S2 = (float)c2 * elu[j0 + 2];
        S3 = (float)c3 * elu[j0 + 3];
    }
    ((float4*)redS[r8])[g] = make_float4(S0, S1, S2, S3);
    __syncthreads();

    if (tid < 128) {
        float s = 0.f;
#pragma unroll
        for (int r = 0; r < 8; r++) s += redS[r][tid];
        invS[tid] = (s > 0.f) ? (1.0f / s) : 0.f;
        addS[tid] = (s > 0.f) ? 0.f : 0.0078125f;   // all-masked col -> uniform
    }
    __syncthreads();

    // -- phase D: float4 write-out --
    const float i0 = invS[j0],     i1 = invS[j0 + 1];
    const float i2 = invS[j0 + 2], i3 = invS[j0 + 3];
    const float a0 = addS[j0],     a1 = addS[j0 + 1];
    const float a2 = addS[j0 + 2], a3 = addS[j0 + 3];
    float4* outp = (float4*)(out + (size_t)b * 16384) + r8 * 16 * 32 + g;

    if (r8 < 4) {
        const int jhi = g >> 4;
        const int ibase = r8 * 16;
#pragma unroll
        for (int rr = 0; rr < 16; rr++) {
            float ev = elt[2 * (ibase + rr) + jhi];
            float4 v;
            v.x = (((m01 >> rr) & 1u)        ? ev * i0 : 0.f) + a0;
            v.y = (((m01 >> (16 + rr)) & 1u) ? ev * i1 : 0.f) + a1;
            v.z = (((m23 >> rr) & 1u)        ? ev * i2 : 0.f) + a2;
            v.w = (((m23 >> (16 + rr)) & 1u) ? ev * i3 : 0.f) + a3;
            outp[rr * 32] = v;
        }
    } else {
        const float e0 = elu[j0] * i0,     e1 = elu[j0 + 1] * i1;
        const float e2 = elu[j0 + 2] * i2, e3 = elu[j0 + 3] * i3;
#pragma unroll
        for (int rr = 0; rr < 16; rr++) {
            float4 v;
            v.x = (((m01 >> rr) & 1u)        ? e0 : 0.f) + a0;
            v.y = (((m01 >> (16 + rr)) & 1u) ? e1 : 0.f) + a1;
            v.z = (((m23 >> rr) & 1u)        ? e2 : 0.f) + a2;
            v.w = (((m23 >> (16 + rr)) & 1u) ? e3 : 0.f) + a3;
            outp[rr * 32] = v;
        }
    }
}

// ---------------- launcher ----------------
extern "C" void kernel_launch(void* const* d_in, const int* in_sizes, int n_in,
                              void* d_out, int out_size) {
    const float* src = (const float*)d_in[0];   // (2048,128,256)
    const float* W   = (const float*)d_in[1];   // (256,256)
    const float* a   = (const float*)d_in[2];   // (512,1)
    const float* adj = (const float*)d_in[3];   // (2048,128,128)
    float* out = (float*)d_out;                 // (2048,128,128)

    prep_v_kernel<<<32, 256>>>(W, a);
    prep_pos_kernel<<<128, 128>>>();
    gat_kernel<<<2048, 256>>>(src, adj, out);
}